// round 11
// baseline (speedup 1.0000x reference)
#include <cuda_runtime.h>
#include <cstdint>

// ============================================================================
// KMeans (Lloyd): N=200000, D=64, K=256, max_iter=10, early-stop move<0.1.
//
// KEY FIX (R11): output labels are written as FLOAT32. All seven scored rounds
// printed bit-identical rel_err 1.000000e+00 because int32 label writes
// reinterpret as float denormals (~1e-43 ~= 0), making ||out-ref||/||ref||
// exactly 1.0 regardless of kernel content. The stub's output examples are
// float/bf16 only; the reference's argmin labels are evidently stored as f32.
//
// Pipeline (deterministic, numerics-faithful to the JAX reference):
//   assign : d2 = (data_sq - 2*dot) + c_sq, fp32, first-min argmin.
//   sums   : deterministic blocked segmented reduction (no float atomics).
//   update : where(cnt>0, s/max(cnt,1), old); moved = max_k ||dc||; done<0.1.
// Early stop via device flag gating a fixed 10-iteration launch sequence.
// ============================================================================

#define KC     256
#define DIMS   64
#define NTA    256
#define HALF_K 128
#define NSB    200

__device__ float g_cent[KC * DIMS];            // [k][d]
__device__ float g_csq[KC];                    // sum(c*c)
__device__ float g_partial[NSB][KC][DIMS];     // per-block partial sums
__device__ float g_diffsq[KC * DIMS];
__device__ int   g_lab[200000];                // int labels (internal)
__device__ int   g_counts[KC];
__device__ int   g_done;
__device__ int   g_mi;

// ---------------------------------------------------------------------------
__global__ void init_kernel(const float* __restrict__ cent_in,
                            const int*   __restrict__ mit) {
    int i = blockIdx.x * blockDim.x + threadIdx.x;
    if (i < KC * DIMS) g_cent[i] = cent_in[i];
    if (i < KC) {
        g_counts[i] = 0;
        float s = 0.0f;
        for (int d = 0; d < DIMS; d++) {
            float c = cent_in[i * DIMS + d];
            s = __fadd_rn(s, __fmul_rn(c, c));
        }
        g_csq[i] = s;
    }
    if (i == 0) {
        g_done = 0;
        int m = mit ? *mit : 10;
        if (m < 0 || m > 1000) m = 10;
        g_mi = m;
    }
}

// ---------------------------------------------------------------------------
__global__ __launch_bounds__(NTA)
void assign_kernel(const float* __restrict__ data, int iter,
                   float* __restrict__ out, int N) {
    if (g_done || iter >= g_mi) return;

    __shared__ float4 s_c4[HALF_K * 16];   // 32 KB: 128 centroids x 64 dims
    __shared__ float  s_cq[HALF_K];

    const int t = threadIdx.x;
    const int n = blockIdx.x * NTA + t;
    const bool valid = (n < N);

    float4 xr[16];
    float  dsq = 0.0f;
    if (valid) {
        const float4* row = (const float4*)(data + (size_t)n * DIMS);
#pragma unroll
        for (int i = 0; i < 16; i++) xr[i] = row[i];
#pragma unroll
        for (int i = 0; i < 16; i++) {
            dsq = __fadd_rn(dsq, __fmul_rn(xr[i].x, xr[i].x));
            dsq = __fadd_rn(dsq, __fmul_rn(xr[i].y, xr[i].y));
            dsq = __fadd_rn(dsq, __fmul_rn(xr[i].z, xr[i].z));
            dsq = __fadd_rn(dsq, __fmul_rn(xr[i].w, xr[i].w));
        }
    }

    float best  = 3.4e38f;
    int   bestk = 0;

#pragma unroll 1
    for (int h = 0; h < 2; h++) {
        const float4* src = (const float4*)(g_cent + h * HALF_K * DIMS);
        for (int i = t; i < HALF_K * 16; i += NTA) s_c4[i] = src[i];
        for (int i = t; i < HALF_K;      i += NTA) s_cq[i] = g_csq[h * HALF_K + i];
        __syncthreads();

        if (valid) {
#pragma unroll 1
            for (int k0 = 0; k0 < HALF_K; k0 += 8) {
                float acc[8];
#pragma unroll
                for (int j = 0; j < 8; j++) acc[j] = 0.0f;
#pragma unroll
                for (int i = 0; i < 16; i++) {
                    const float4 xv = xr[i];
#pragma unroll
                    for (int j = 0; j < 8; j++) {
                        const float4 c = s_c4[(k0 + j) * 16 + i];
                        float a = acc[j];
                        a = fmaf(xv.x, c.x, a);
                        a = fmaf(xv.y, c.y, a);
                        a = fmaf(xv.z, c.z, a);
                        a = fmaf(xv.w, c.w, a);
                        acc[j] = a;
                    }
                }
#pragma unroll
                for (int j = 0; j < 8; j++) {
                    float t2 = __fmul_rn(2.0f, acc[j]);
                    float u  = __fsub_rn(dsq, t2);
                    float d2 = __fadd_rn(u, s_cq[k0 + j]);   // (dsq-2G)+csq
                    int   kk = h * HALF_K + k0 + j;
                    if (d2 < best) { best = d2; bestk = kk; } // first-min
                }
            }
        }
        __syncthreads();
    }

    if (valid) {
        g_lab[n] = bestk;
        out[n]   = (float)bestk;     // OUTPUT AS FLOAT32 (the fix)
    }
}

// ---------------------------------------------------------------------------
// Deterministic segmented sum: block b owns a contiguous point chunk, thread t
// owns dim t, sequential over points; two 128-cluster smem halves.
__global__ __launch_bounds__(64)
void sums_kernel(const float* __restrict__ data, int iter, int N) {
    if (g_done || iter >= g_mi) return;

    __shared__ float s_sum[HALF_K][DIMS];   // 32 KB
    const int t = threadIdx.x;              // dim
    const int b = blockIdx.x;
    const int chunk = (N + NSB - 1) / NSB;
    const int n0 = b * chunk;
    const int n1 = (n0 + chunk < N) ? (n0 + chunk) : N;

#pragma unroll 1
    for (int h = 0; h < 2; h++) {
        for (int i = t; i < HALF_K * DIMS; i += 64) (&s_sum[0][0])[i] = 0.0f;
        __syncthreads();
#pragma unroll 1
        for (int n = n0; n < n1; n++) {
            int l = g_lab[n];
            if (h == 0 && t == 0) atomicAdd(&g_counts[l], 1);   // int: determ.
            int lh = l - h * HALF_K;
            if (lh >= 0 && lh < HALF_K) {
                float x = data[(size_t)n * DIMS + t];
                s_sum[lh][t] = __fadd_rn(s_sum[lh][t], x);
            }
        }
        __syncthreads();
        for (int i = t; i < HALF_K * DIMS; i += 64) {
            int kk = i / DIMS, dd = i % DIMS;
            g_partial[b][h * HALF_K + kk][dd] = s_sum[kk][dd];
        }
        __syncthreads();
    }
}

__global__ void reduceA_kernel(int iter) {      // 64 x 256
    if (g_done || iter >= g_mi) return;
    int idx = blockIdx.x * blockDim.x + threadIdx.x;   // 0..16383
    int k = idx / DIMS, d = idx % DIMS;
    float s = 0.0f;
#pragma unroll 1
    for (int b = 0; b < NSB; b++) s = __fadd_rn(s, g_partial[b][k][d]);
    int   cnt = g_counts[k];
    float old = g_cent[idx];
    float cf  = fmaxf((float)cnt, 1.0f);
    float nc  = (cnt > 0) ? __fdiv_rn(s, cf) : old;
    g_cent[idx] = nc;
    float df = __fsub_rn(nc, old);
    g_diffsq[idx] = __fmul_rn(df, df);
}

__global__ void reduceB_kernel(int iter) {      // 1 x 256
    if (g_done || iter >= g_mi) return;
    __shared__ float s_mv[KC];
    int k = threadIdx.x;
    float msq = 0.0f;
    for (int d = 0; d < DIMS; d++) msq = __fadd_rn(msq, g_diffsq[k * DIMS + d]);
    s_mv[k] = __fsqrt_rn(msq);                  // ||new-old||
    float cs = 0.0f;
    for (int d = 0; d < DIMS; d++) {
        float c = g_cent[k * DIMS + d];
        cs = __fadd_rn(cs, __fmul_rn(c, c));
    }
    g_csq[k]    = cs;
    g_counts[k] = 0;
    __syncthreads();
    if (k == 0) {
        float m = 0.0f;
        for (int i = 0; i < KC; i++) m = fmaxf(m, s_mv[i]);
        if (m < 0.1f) g_done = 1;               // moved < 0.1
    }
}

// ---------------------------------------------------------------------------
extern "C" void kernel_launch(void* const* d_in, const int* in_sizes, int n_in,
                              void* d_out, int out_size) {
    const float* data = nullptr;
    const float* cent = nullptr;
    const int*   mit  = nullptr;
    int data_elems = 0;
    for (int i = 0; i < n_in; i++) {
        int sz = in_sizes[i];
        if (sz == KC * DIMS && !cent)        cent = (const float*)d_in[i];
        else if (sz > KC * DIMS && !data)  { data = (const float*)d_in[i]; data_elems = sz; }
        else if (sz >= 1 && sz <= 2 && !mit) mit  = (const int*)d_in[i];
    }
    if (!data) { data = (const float*)d_in[0]; data_elems = in_sizes[0]; }
    if (!cent && n_in > 1) cent = (const float*)d_in[1];

    float* out = (float*)d_out;                 // FLOAT32 output
    const int N       = data_elems / DIMS;
    const int ablocks = (N + NTA - 1) / NTA;

    init_kernel<<<(KC * DIMS + 255) / 256, 256>>>(cent, mit);

    for (int it = 0; it < 10; it++) {
        assign_kernel<<<ablocks, NTA>>>(data, it, out, N);
        sums_kernel<<<NSB, 64>>>(data, it, N);
        reduceA_kernel<<<64, 256>>>(it);
        reduceB_kernel<<<1, KC>>>(it);
    }
}

// round 12
// speedup vs baseline: 1.8837x; 1.8837x over previous
#include <cuda_runtime.h>
#include <cstdint>

// ============================================================================
// KMeans (Lloyd): N=200000, D=64, K=256, max_iter=10, early-stop move<0.1.
// R11 passed (rel_err 0.0, 7527us). R12: bit-exact-preserving perf fixes:
//   - sums: single-pass 65KB dynamic smem, x8 unrolled batched loads
//           (same per-accumulator ascending-n add order => identical bits)
//   - reduceA: [k][d][b] contiguous partials, sequential accumulator
//   - reduceB: tree max (exact), unrolled
//   - assign: UNCHANGED (bit-exact anchor; f32x2 2x is next round's isolated
//     experiment)
// ============================================================================

#define KC     256
#define DIMS   64
#define NTA    256
#define HALF_K 128
#define NSB    200

__device__ float g_cent[KC * DIMS];            // [k][d]
__device__ float g_csq[KC];                    // sum(c*c)
__device__ float g_partial[KC * DIMS * NSB];   // [k][d][b]  (b contiguous)
__device__ float g_diffsq[KC * DIMS];
__device__ int   g_lab[200000];
__device__ int   g_counts[KC];
__device__ int   g_done;
__device__ int   g_mi;

// ---------------------------------------------------------------------------
__global__ void init_kernel(const float* __restrict__ cent_in,
                            const int*   __restrict__ mit) {
    int i = blockIdx.x * blockDim.x + threadIdx.x;
    if (i < KC * DIMS) g_cent[i] = cent_in[i];
    if (i < KC) {
        g_counts[i] = 0;
        float s = 0.0f;
        for (int d = 0; d < DIMS; d++) {
            float c = cent_in[i * DIMS + d];
            s = __fadd_rn(s, __fmul_rn(c, c));
        }
        g_csq[i] = s;
    }
    if (i == 0) {
        g_done = 0;
        int m = mit ? *mit : 10;
        if (m < 0 || m > 1000) m = 10;
        g_mi = m;
    }
}

// --------------------------- assign (unchanged) ----------------------------
__global__ __launch_bounds__(NTA)
void assign_kernel(const float* __restrict__ data, int iter,
                   float* __restrict__ out, int N) {
    if (g_done || iter >= g_mi) return;

    __shared__ float4 s_c4[HALF_K * 16];   // 32 KB
    __shared__ float  s_cq[HALF_K];

    const int t = threadIdx.x;
    const int n = blockIdx.x * NTA + t;
    const bool valid = (n < N);

    float4 xr[16];
    float  dsq = 0.0f;
    if (valid) {
        const float4* row = (const float4*)(data + (size_t)n * DIMS);
#pragma unroll
        for (int i = 0; i < 16; i++) xr[i] = row[i];
#pragma unroll
        for (int i = 0; i < 16; i++) {
            dsq = __fadd_rn(dsq, __fmul_rn(xr[i].x, xr[i].x));
            dsq = __fadd_rn(dsq, __fmul_rn(xr[i].y, xr[i].y));
            dsq = __fadd_rn(dsq, __fmul_rn(xr[i].z, xr[i].z));
            dsq = __fadd_rn(dsq, __fmul_rn(xr[i].w, xr[i].w));
        }
    }

    float best  = 3.4e38f;
    int   bestk = 0;

#pragma unroll 1
    for (int h = 0; h < 2; h++) {
        const float4* src = (const float4*)(g_cent + h * HALF_K * DIMS);
        for (int i = t; i < HALF_K * 16; i += NTA) s_c4[i] = src[i];
        for (int i = t; i < HALF_K;      i += NTA) s_cq[i] = g_csq[h * HALF_K + i];
        __syncthreads();

        if (valid) {
#pragma unroll 1
            for (int k0 = 0; k0 < HALF_K; k0 += 8) {
                float acc[8];
#pragma unroll
                for (int j = 0; j < 8; j++) acc[j] = 0.0f;
#pragma unroll
                for (int i = 0; i < 16; i++) {
                    const float4 xv = xr[i];
#pragma unroll
                    for (int j = 0; j < 8; j++) {
                        const float4 c = s_c4[(k0 + j) * 16 + i];
                        float a = acc[j];
                        a = fmaf(xv.x, c.x, a);
                        a = fmaf(xv.y, c.y, a);
                        a = fmaf(xv.z, c.z, a);
                        a = fmaf(xv.w, c.w, a);
                        acc[j] = a;
                    }
                }
#pragma unroll
                for (int j = 0; j < 8; j++) {
                    float t2 = __fmul_rn(2.0f, acc[j]);
                    float u  = __fsub_rn(dsq, t2);
                    float d2 = __fadd_rn(u, s_cq[k0 + j]);
                    int   kk = h * HALF_K + k0 + j;
                    if (d2 < best) { best = d2; bestk = kk; }
                }
            }
        }
        __syncthreads();
    }

    if (valid) {
        g_lab[n] = bestk;
        out[n]   = (float)bestk;     // FLOAT32 output
    }
}

// --------------------- sums: single pass, dynamic smem ---------------------
// smem: 256*64 floats (64KB) + 256 ints (1KB)
#define SUMS_SMEM ((KC * DIMS) * 4 + KC * 4)

__global__ __launch_bounds__(64)
void sums_fused(const float* __restrict__ data, int iter, int N) {
    if (g_done || iter >= g_mi) return;

    extern __shared__ float s_sum[];              // [256*64]
    int* s_cnt = (int*)(s_sum + KC * DIMS);       // [256]

    const int t = threadIdx.x;                    // dim 0..63
    const int b = blockIdx.x;
    const int chunk = (N + NSB - 1) / NSB;
    const int n0 = b * chunk;
    const int n1 = (n0 + chunk < N) ? (n0 + chunk) : N;

    for (int i = t; i < KC * DIMS; i += 64) s_sum[i] = 0.0f;
    for (int i = t; i < KC;        i += 64) s_cnt[i] = 0;
    __syncthreads();

    int n = n0;
#pragma unroll 1
    for (; n + 8 <= n1; n += 8) {
        int   l[8];
        float x[8];
#pragma unroll
        for (int j = 0; j < 8; j++) l[j] = g_lab[n + j];
#pragma unroll
        for (int j = 0; j < 8; j++) x[j] = data[(size_t)(n + j) * DIMS + t];
#pragma unroll
        for (int j = 0; j < 8; j++) {             // ascending n: bit-exact order
            int a = l[j] * DIMS + t;
            s_sum[a] = __fadd_rn(s_sum[a], x[j]);
        }
        if (t == 0) {
#pragma unroll
            for (int j = 0; j < 8; j++) s_cnt[l[j]]++;
        }
    }
#pragma unroll 1
    for (; n < n1; n++) {                         // tail
        int l = g_lab[n];
        float x = data[(size_t)n * DIMS + t];
        int a = l * DIMS + t;
        s_sum[a] = __fadd_rn(s_sum[a], x);
        if (t == 0) s_cnt[l]++;
    }
    __syncthreads();

    for (int i = t; i < KC * DIMS; i += 64)
        g_partial[(size_t)i * NSB + b] = s_sum[i];
    for (int i = t; i < KC; i += 64) {
        int c = s_cnt[i];
        if (c) atomicAdd(&g_counts[i], c);        // int: order-exact
    }
}

// Fallback (static smem, 2-pass) if the 65KB dynamic opt-in fails.
__global__ __launch_bounds__(64)
void sums_fallback(const float* __restrict__ data, int iter, int N) {
    if (g_done || iter >= g_mi) return;
    __shared__ float s_sum[HALF_K * DIMS];        // 32 KB
    const int t = threadIdx.x;
    const int b = blockIdx.x;
    const int chunk = (N + NSB - 1) / NSB;
    const int n0 = b * chunk;
    const int n1 = (n0 + chunk < N) ? (n0 + chunk) : N;
#pragma unroll 1
    for (int h = 0; h < 2; h++) {
        for (int i = t; i < HALF_K * DIMS; i += 64) s_sum[i] = 0.0f;
        __syncthreads();
#pragma unroll 1
        for (int n = n0; n < n1; n++) {
            int l = g_lab[n];
            if (h == 0 && t == 0) atomicAdd(&g_counts[l], 1);
            int lh = l - h * HALF_K;
            if (lh >= 0 && lh < HALF_K) {
                float x = data[(size_t)n * DIMS + t];
                s_sum[lh * DIMS + t] = __fadd_rn(s_sum[lh * DIMS + t], x);
            }
        }
        __syncthreads();
        for (int i = t; i < HALF_K * DIMS; i += 64)
            g_partial[(size_t)(h * HALF_K * DIMS + i) * NSB + b] = s_sum[i];
        __syncthreads();
    }
}

// ----------------------- reduceA: contiguous partials ----------------------
__global__ void reduceA_kernel(int iter) {        // 64 x 256
    if (g_done || iter >= g_mi) return;
    int idx = blockIdx.x * blockDim.x + threadIdx.x;    // (k*64+d)
    const float* p = g_partial + (size_t)idx * NSB;
    float s = 0.0f;
#pragma unroll 8
    for (int b = 0; b < NSB; b++) s = __fadd_rn(s, p[b]);  // ascending b
    int k = idx / DIMS;
    int   cnt = g_counts[k];
    float old = g_cent[idx];
    float cf  = fmaxf((float)cnt, 1.0f);
    float nc  = (cnt > 0) ? __fdiv_rn(s, cf) : old;
    g_cent[idx] = nc;
    float df = __fsub_rn(nc, old);
    g_diffsq[idx] = __fmul_rn(df, df);
}

// -------------------------- reduceB: tree max ------------------------------
__global__ void reduceB_kernel(int iter) {        // 1 x 256
    if (g_done || iter >= g_mi) return;
    __shared__ float s_mv[KC];
    int k = threadIdx.x;

    float msq = 0.0f;
#pragma unroll 8
    for (int d = 0; d < DIMS; d++) msq = __fadd_rn(msq, g_diffsq[k * DIMS + d]);
    s_mv[k] = __fsqrt_rn(msq);

    float cs = 0.0f;
#pragma unroll 8
    for (int d = 0; d < DIMS; d++) {
        float c = g_cent[k * DIMS + d];
        cs = __fadd_rn(cs, __fmul_rn(c, c));
    }
    g_csq[k]    = cs;
    g_counts[k] = 0;
    __syncthreads();

    for (int off = 128; off > 0; off >>= 1) {     // max: order-exact
        if (k < off) s_mv[k] = fmaxf(s_mv[k], s_mv[k + off]);
        __syncthreads();
    }
    if (k == 0 && s_mv[0] < 0.1f) g_done = 1;
}

// ---------------------------------------------------------------------------
extern "C" void kernel_launch(void* const* d_in, const int* in_sizes, int n_in,
                              void* d_out, int out_size) {
    const float* data = nullptr;
    const float* cent = nullptr;
    const int*   mit  = nullptr;
    int data_elems = 0;
    for (int i = 0; i < n_in; i++) {
        int sz = in_sizes[i];
        if (sz == KC * DIMS && !cent)        cent = (const float*)d_in[i];
        else if (sz > KC * DIMS && !data)  { data = (const float*)d_in[i]; data_elems = sz; }
        else if (sz >= 1 && sz <= 2 && !mit) mit  = (const int*)d_in[i];
    }
    if (!data) { data = (const float*)d_in[0]; data_elems = in_sizes[0]; }
    if (!cent && n_in > 1) cent = (const float*)d_in[1];

    float* out = (float*)d_out;
    const int N       = data_elems / DIMS;
    const int ablocks = (N + NTA - 1) / NTA;

    static bool attr_done = false, big_ok = false;
    if (!attr_done) {
        big_ok = (cudaFuncSetAttribute(sums_fused,
                      cudaFuncAttributeMaxDynamicSharedMemorySize,
                      SUMS_SMEM) == cudaSuccess);
        attr_done = true;
    }

    init_kernel<<<(KC * DIMS + 255) / 256, 256>>>(cent, mit);

    for (int it = 0; it < 10; it++) {
        assign_kernel<<<ablocks, NTA>>>(data, it, out, N);
        if (big_ok) sums_fused<<<NSB, 64, SUMS_SMEM>>>(data, it, N);
        else        sums_fallback<<<NSB, 64>>>(data, it, N);
        reduceA_kernel<<<64, 256>>>(it);
        reduceB_kernel<<<1, KC>>>(it);
    }
}

// round 15
// speedup vs baseline: 2.0383x; 1.0821x over previous
#include <cuda_runtime.h>
#include <cstdint>

// ============================================================================
// KMeans (Lloyd): N=200000, D=64, K=256, max_iter=10, early-stop move<0.1.
// R14: f32x2 produced garbage (rel_err 0.712 ~= uncorrelated labels) - BANNED.
// R15: revert to R12's bit-exact scalar fmaf assign math; make assign
// PERSISTENT: 2 blocks/SM x 256 thr, all 256 centroids in 66KB dynamic smem
// loaded once, sync-free grid-stride point loop (kills per-point half-reloads,
// syncs, and the 5.3-wave tail). Per-point FFMA order/k-scan/tie-break are
// instruction-identical to R12 => labels bit-identical.
// sums/reduceA/reduceB byte-identical to R12 (3996us baseline).
// ============================================================================

#define KC     256
#define DIMS   64
#define NTA    256
#define HALF_K 128
#define NSB    200
#define NBP    296                       // persistent blocks (2/SM)

__device__ float g_cent[KC * DIMS];            // [k][d]
__device__ float g_csq[KC];                    // sum(c*c)
__device__ float g_partial[KC * DIMS * NSB];   // [k][d][b]
__device__ float g_diffsq[KC * DIMS];
__device__ int   g_lab[200000];
__device__ int   g_counts[KC];
__device__ int   g_done;
__device__ int   g_mi;

// ---------------------------------------------------------------------------
__global__ void init_kernel(const float* __restrict__ cent_in,
                            const int*   __restrict__ mit) {
    int i = blockIdx.x * blockDim.x + threadIdx.x;
    if (i < KC * DIMS) g_cent[i] = cent_in[i];
    if (i < KC) {
        g_counts[i] = 0;
        float s = 0.0f;
        for (int d = 0; d < DIMS; d++) {
            float c = cent_in[i * DIMS + d];
            s = __fadd_rn(s, __fmul_rn(c, c));
        }
        g_csq[i] = s;
    }
    if (i == 0) {
        g_done = 0;
        int m = mit ? *mit : 10;
        if (m < 0 || m > 1000) m = 10;
        g_mi = m;
    }
}

// --------------- assign: persistent, all centroids resident ----------------
// dyn smem: 256*64 floats (centroids as float4[256*16]) + 256 floats (csq)
#define ASSIGN_SMEM ((KC * DIMS + KC) * 4)

__global__ __launch_bounds__(NTA)
void assign_persist(const float* __restrict__ data, int iter,
                    float* __restrict__ out, int N) {
    if (g_done || iter >= g_mi) return;

    extern __shared__ float4 s_dyn[];
    float4* s_c4 = s_dyn;                        // [KC*16]
    float*  s_cq = (float*)(s_dyn + KC * 16);    // [KC]

    const int t = threadIdx.x;
    { // load ALL centroids once
        const float4* src = (const float4*)g_cent;
        for (int i = t; i < KC * 16; i += NTA) s_c4[i] = src[i];
        for (int i = t; i < KC;      i += NTA) s_cq[i] = g_csq[i];
    }
    __syncthreads();

    const int start  = blockIdx.x * NTA + t;
    const int stride = NBP * NTA;

#pragma unroll 1
    for (int n = start; n < N; n += stride) {
        float4 xr[16];
        const float4* row = (const float4*)(data + (size_t)n * DIMS);
#pragma unroll
        for (int i = 0; i < 16; i++) xr[i] = row[i];

        float dsq = 0.0f;
#pragma unroll
        for (int i = 0; i < 16; i++) {
            dsq = __fadd_rn(dsq, __fmul_rn(xr[i].x, xr[i].x));
            dsq = __fadd_rn(dsq, __fmul_rn(xr[i].y, xr[i].y));
            dsq = __fadd_rn(dsq, __fmul_rn(xr[i].z, xr[i].z));
            dsq = __fadd_rn(dsq, __fmul_rn(xr[i].w, xr[i].w));
        }

        float best  = 3.4e38f;
        int   bestk = 0;

#pragma unroll 1
        for (int k0 = 0; k0 < KC; k0 += 8) {     // same ascending k-scan
            float acc[8];
#pragma unroll
            for (int j = 0; j < 8; j++) acc[j] = 0.0f;
#pragma unroll
            for (int i = 0; i < 16; i++) {
                const float4 xv = xr[i];
#pragma unroll
                for (int j = 0; j < 8; j++) {
                    const float4 c = s_c4[(k0 + j) * 16 + i];
                    float a = acc[j];
                    a = fmaf(xv.x, c.x, a);       // identical chain to R12
                    a = fmaf(xv.y, c.y, a);
                    a = fmaf(xv.z, c.z, a);
                    a = fmaf(xv.w, c.w, a);
                    acc[j] = a;
                }
            }
#pragma unroll
            for (int j = 0; j < 8; j++) {
                float t2 = __fmul_rn(2.0f, acc[j]);
                float u  = __fsub_rn(dsq, t2);
                float d2 = __fadd_rn(u, s_cq[k0 + j]);
                int   kk = k0 + j;
                if (d2 < best) { best = d2; bestk = kk; }  // first-min
            }
        }

        g_lab[n] = bestk;
        out[n]   = (float)bestk;                 // FLOAT32 output
    }
}

// Fallback: R12's two-half static-smem assign (bit-identical math).
__global__ __launch_bounds__(NTA)
void assign_fallback(const float* __restrict__ data, int iter,
                     float* __restrict__ out, int N) {
    if (g_done || iter >= g_mi) return;
    __shared__ float4 s_c4[HALF_K * 16];
    __shared__ float  s_cq[HALF_K];
    const int t = threadIdx.x;
    const int n = blockIdx.x * NTA + t;
    const bool valid = (n < N);

    float4 xr[16];
    float  dsq = 0.0f;
    if (valid) {
        const float4* row = (const float4*)(data + (size_t)n * DIMS);
#pragma unroll
        for (int i = 0; i < 16; i++) xr[i] = row[i];
#pragma unroll
        for (int i = 0; i < 16; i++) {
            dsq = __fadd_rn(dsq, __fmul_rn(xr[i].x, xr[i].x));
            dsq = __fadd_rn(dsq, __fmul_rn(xr[i].y, xr[i].y));
            dsq = __fadd_rn(dsq, __fmul_rn(xr[i].z, xr[i].z));
            dsq = __fadd_rn(dsq, __fmul_rn(xr[i].w, xr[i].w));
        }
    }
    float best = 3.4e38f; int bestk = 0;
#pragma unroll 1
    for (int h = 0; h < 2; h++) {
        const float4* src = (const float4*)(g_cent + h * HALF_K * DIMS);
        for (int i = t; i < HALF_K * 16; i += NTA) s_c4[i] = src[i];
        for (int i = t; i < HALF_K;      i += NTA) s_cq[i] = g_csq[h * HALF_K + i];
        __syncthreads();
        if (valid) {
#pragma unroll 1
            for (int k0 = 0; k0 < HALF_K; k0 += 8) {
                float acc[8];
#pragma unroll
                for (int j = 0; j < 8; j++) acc[j] = 0.0f;
#pragma unroll
                for (int i = 0; i < 16; i++) {
                    const float4 xv = xr[i];
#pragma unroll
                    for (int j = 0; j < 8; j++) {
                        const float4 c = s_c4[(k0 + j) * 16 + i];
                        float a = acc[j];
                        a = fmaf(xv.x, c.x, a);
                        a = fmaf(xv.y, c.y, a);
                        a = fmaf(xv.z, c.z, a);
                        a = fmaf(xv.w, c.w, a);
                        acc[j] = a;
                    }
                }
#pragma unroll
                for (int j = 0; j < 8; j++) {
                    float t2 = __fmul_rn(2.0f, acc[j]);
                    float u  = __fsub_rn(dsq, t2);
                    float d2 = __fadd_rn(u, s_cq[k0 + j]);
                    int   kk = h * HALF_K + k0 + j;
                    if (d2 < best) { best = d2; bestk = kk; }
                }
            }
        }
        __syncthreads();
    }
    if (valid) { g_lab[n] = bestk; out[n] = (float)bestk; }
}

// --------------------- sums: single pass, dynamic smem ---------------------
#define SUMS_SMEM ((KC * DIMS) * 4 + KC * 4)

__global__ __launch_bounds__(64)
void sums_fused(const float* __restrict__ data, int iter, int N) {
    if (g_done || iter >= g_mi) return;

    extern __shared__ float s_sum[];              // [256*64]
    int* s_cnt = (int*)(s_sum + KC * DIMS);       // [256]

    const int t = threadIdx.x;
    const int b = blockIdx.x;
    const int chunk = (N + NSB - 1) / NSB;
    const int n0 = b * chunk;
    const int n1 = (n0 + chunk < N) ? (n0 + chunk) : N;

    for (int i = t; i < KC * DIMS; i += 64) s_sum[i] = 0.0f;
    for (int i = t; i < KC;        i += 64) s_cnt[i] = 0;
    __syncthreads();

    int n = n0;
#pragma unroll 1
    for (; n + 8 <= n1; n += 8) {
        int   l[8];
        float x[8];
#pragma unroll
        for (int j = 0; j < 8; j++) l[j] = g_lab[n + j];
#pragma unroll
        for (int j = 0; j < 8; j++) x[j] = data[(size_t)(n + j) * DIMS + t];
#pragma unroll
        for (int j = 0; j < 8; j++) {
            int a = l[j] * DIMS + t;
            s_sum[a] = __fadd_rn(s_sum[a], x[j]);
        }
        if (t == 0) {
#pragma unroll
            for (int j = 0; j < 8; j++) s_cnt[l[j]]++;
        }
    }
#pragma unroll 1
    for (; n < n1; n++) {
        int l = g_lab[n];
        float x = data[(size_t)n * DIMS + t];
        int a = l * DIMS + t;
        s_sum[a] = __fadd_rn(s_sum[a], x);
        if (t == 0) s_cnt[l]++;
    }
    __syncthreads();

    for (int i = t; i < KC * DIMS; i += 64)
        g_partial[(size_t)i * NSB + b] = s_sum[i];
    for (int i = t; i < KC; i += 64) {
        int c = s_cnt[i];
        if (c) atomicAdd(&g_counts[i], c);
    }
}

__global__ __launch_bounds__(64)
void sums_fallback(const float* __restrict__ data, int iter, int N) {
    if (g_done || iter >= g_mi) return;
    __shared__ float s_sum[HALF_K * DIMS];
    const int t = threadIdx.x;
    const int b = blockIdx.x;
    const int chunk = (N + NSB - 1) / NSB;
    const int n0 = b * chunk;
    const int n1 = (n0 + chunk < N) ? (n0 + chunk) : N;
#pragma unroll 1
    for (int h = 0; h < 2; h++) {
        for (int i = t; i < HALF_K * DIMS; i += 64) s_sum[i] = 0.0f;
        __syncthreads();
#pragma unroll 1
        for (int n = n0; n < n1; n++) {
            int l = g_lab[n];
            if (h == 0 && t == 0) atomicAdd(&g_counts[l], 1);
            int lh = l - h * HALF_K;
            if (lh >= 0 && lh < HALF_K) {
                float x = data[(size_t)n * DIMS + t];
                s_sum[lh * DIMS + t] = __fadd_rn(s_sum[lh * DIMS + t], x);
            }
        }
        __syncthreads();
        for (int i = t; i < HALF_K * DIMS; i += 64)
            g_partial[(size_t)(h * HALF_K * DIMS + i) * NSB + b] = s_sum[i];
        __syncthreads();
    }
}

// ----------------------- reduceA: contiguous partials ----------------------
__global__ void reduceA_kernel(int iter) {        // 64 x 256
    if (g_done || iter >= g_mi) return;
    int idx = blockIdx.x * blockDim.x + threadIdx.x;
    const float* p = g_partial + (size_t)idx * NSB;
    float s = 0.0f;
#pragma unroll 8
    for (int b = 0; b < NSB; b++) s = __fadd_rn(s, p[b]);
    int k = idx / DIMS;
    int   cnt = g_counts[k];
    float old = g_cent[idx];
    float cf  = fmaxf((float)cnt, 1.0f);
    float nc  = (cnt > 0) ? __fdiv_rn(s, cf) : old;
    g_cent[idx] = nc;
    float df = __fsub_rn(nc, old);
    g_diffsq[idx] = __fmul_rn(df, df);
}

// -------------------------- reduceB: tree max ------------------------------
__global__ void reduceB_kernel(int iter) {        // 1 x 256
    if (g_done || iter >= g_mi) return;
    __shared__ float s_mv[KC];
    int k = threadIdx.x;

    float msq = 0.0f;
#pragma unroll 8
    for (int d = 0; d < DIMS; d++) msq = __fadd_rn(msq, g_diffsq[k * DIMS + d]);
    s_mv[k] = __fsqrt_rn(msq);

    float cs = 0.0f;
#pragma unroll 8
    for (int d = 0; d < DIMS; d++) {
        float c = g_cent[k * DIMS + d];
        cs = __fadd_rn(cs, __fmul_rn(c, c));
    }
    g_csq[k]    = cs;
    g_counts[k] = 0;
    __syncthreads();

    for (int off = 128; off > 0; off >>= 1) {
        if (k < off) s_mv[k] = fmaxf(s_mv[k], s_mv[k + off]);
        __syncthreads();
    }
    if (k == 0 && s_mv[0] < 0.1f) g_done = 1;
}

// ---------------------------------------------------------------------------
extern "C" void kernel_launch(void* const* d_in, const int* in_sizes, int n_in,
                              void* d_out, int out_size) {
    const float* data = nullptr;
    const float* cent = nullptr;
    const int*   mit  = nullptr;
    int data_elems = 0;
    for (int i = 0; i < n_in; i++) {
        int sz = in_sizes[i];
        if (sz == KC * DIMS && !cent)        cent = (const float*)d_in[i];
        else if (sz > KC * DIMS && !data)  { data = (const float*)d_in[i]; data_elems = sz; }
        else if (sz >= 1 && sz <= 2 && !mit) mit  = (const int*)d_in[i];
    }
    if (!data) { data = (const float*)d_in[0]; data_elems = in_sizes[0]; }
    if (!cent && n_in > 1) cent = (const float*)d_in[1];

    float* out = (float*)d_out;
    const int N       = data_elems / DIMS;
    const int ablocks = (N + NTA - 1) / NTA;

    static bool attr_done = false, sums_ok = false, asn_ok = false;
    if (!attr_done) {
        sums_ok = (cudaFuncSetAttribute(sums_fused,
                       cudaFuncAttributeMaxDynamicSharedMemorySize,
                       SUMS_SMEM) == cudaSuccess);
        asn_ok  = (cudaFuncSetAttribute(assign_persist,
                       cudaFuncAttributeMaxDynamicSharedMemorySize,
                       ASSIGN_SMEM) == cudaSuccess);
        attr_done = true;
    }

    init_kernel<<<(KC * DIMS + 255) / 256, 256>>>(cent, mit);

    for (int it = 0; it < 10; it++) {
        if (asn_ok) assign_persist<<<NBP, NTA, ASSIGN_SMEM>>>(data, it, out, N);
        else        assign_fallback<<<ablocks, NTA>>>(data, it, out, N);
        if (sums_ok) sums_fused<<<NSB, 64, SUMS_SMEM>>>(data, it, N);
        else         sums_fallback<<<NSB, 64>>>(data, it, N);
        reduceA_kernel<<<64, 256>>>(it);
        reduceB_kernel<<<1, KC>>>(it);
    }
}